// round 8
// baseline (speedup 1.0000x reference)
#include <cuda_runtime.h>
#include <math.h>

#define IMG   512
#define PIX   (IMG * IMG)
#define NIMG  64
#define TX    128
#define PADW  (TX + 12)
#define NSTRIP 128                  // 32 image-pairs x 4 column strips
#define NJOB  (NSTRIP * IMG)        // 65536 output rows
#define NBLK  444                   // 148 SMs x 3 resident CTAs -> single wave
#define NBIG  268                   // 268*148 + 176*147 = 65536
#define CBIG  148
#define CSML  147

typedef unsigned long long u64;

__device__ double g_part[NBLK];
__device__ int    g_cnt;            // zero-initialized; self-resets each launch

static __device__ __forceinline__ u64 pk2(float a, float b) {
    u64 r; asm("mov.b64 %0, {%1, %2};" : "=l"(r) : "f"(a), "f"(b)); return r;
}
static __device__ __forceinline__ void unpk2(u64 v, float& a, float& b) {
    asm("mov.b64 {%0, %1}, %2;" : "=f"(a), "=f"(b) : "l"(v));
}
static __device__ __forceinline__ u64 f2add(u64 a, u64 b) {
    u64 d; asm("add.rn.f32x2 %0, %1, %2;" : "=l"(d) : "l"(a), "l"(b)); return d;
}
static __device__ __forceinline__ u64 f2mul(u64 a, u64 b) {
    u64 d; asm("mul.rn.f32x2 %0, %1, %2;" : "=l"(d) : "l"(a), "l"(b)); return d;
}
static __device__ __forceinline__ u64 f2fma(u64 a, u64 b, u64 c) {
    u64 d; asm("fma.rn.f32x2 %0, %1, %2, %3;" : "=l"(d) : "l"(a), "l"(b), "l"(c)); return d;
}

__global__ void __launch_bounds__(TX, 3) ssim_main(
    const float* __restrict__ pred, const float* __restrict__ gt,
    float* __restrict__ out)
{
    // Persistent-balanced version of the R6 pair-pipeline: 444 blocks (one
    // wave), each streams ~148 contiguous output rows, re-warming the 11-row
    // ring only at strip crossings. Removes the 2.31->3 wave quantization
    // (~23% idle) of the 1024-block grid.
    __shared__ float4 sv[2][2][PADW];
    __shared__ float wred[TX / 32];
    __shared__ int   slast;

    const int tid = threadIdx.x;
    const int b   = blockIdx.x;

    // Gaussian 1D weights (sigma = 11/6, normalized) — same math as reference
    float w[6];
    {
        const float sig = 11.0f / 6.0f;
        const float inv = 1.0f / (2.0f * sig * sig);
        float e[6];
        #pragma unroll
        for (int d = 0; d < 6; ++d) e[d] = expf(-(float)(d * d) * inv);
        float s = e[0] + 2.f * (e[1] + e[2] + e[3] + e[4] + e[5]);
        #pragma unroll
        for (int d = 0; d < 6; ++d) w[d] = e[d] / s;
    }
    u64 w2[6];
    #pragma unroll
    for (int d = 0; d < 6; ++d) w2[d] = pk2(w[d], w[d]);

    const float C1 = 0.01f * 0.01f;
    const float C2 = 0.03f * 0.03f;
    const u64 c1_2  = pk2(C1, C1);
    const u64 c2_2  = pk2(C2, C2);
    const u64 c12_2 = pk2(C1 + C2, C1 + C2);
    const u64 two2  = pk2(2.f, 2.f);
    const u64 n2_2  = pk2(-2.f, -2.f);
    const u64 n1_2  = pk2(-1.f, -1.f);

    // 11-row ring buffers of horizontally-blurred channels (registers)
    u64 rP[11], rG[11], rS[11], rX[11];
    u64 acc0 = 0ull, acc1 = 0ull;

    // this block's contiguous chunk of output-row jobs
    int       j    = (b < NBIG) ? b * CBIG : NBIG * CBIG + (b - NBIG) * CSML;
    const int jend = j + ((b < NBIG) ? CBIG : CSML);

    while (j < jend) {
        const int s      = j >> 9;                         // strip id
        const int y0     = j & (IMG - 1);                  // first output row
        const int avail  = IMG - y0;
        const int rem    = jend - j;
        const int segout = (rem < avail) ? rem : avail;    // outputs this segment
        const int NIT    = segout + 10;                    // row-iters (incl. warm)
        const int NP     = (NIT + 1) >> 1;                 // pair-iters

        const int im0 = s >> 2;
        const int cx  = (s & 3) * TX;
        const float* p0 = pred + (size_t)im0 * PIX;
        const float* p1 = pred + (size_t)(im0 + NIMG / 2) * PIX;
        const float* g0 = gt   + (size_t)im0 * PIX;
        const float* g1 = gt   + (size_t)(im0 + NIMG / 2) * PIX;

        const int cmain = cx + tid - 5;
        const int chalo = cx + TX + tid - 5;
        const bool cm_in = ((unsigned)cmain < IMG);
        const bool ch_in = ((unsigned)chalo < IMG) && (tid < 10);

        float pmA0, pmA1, gmA0, gmA1, phA0, phA1, ghA0, ghA1;
        float pmB0, pmB1, gmB0, gmB1, phB0, phB1, ghB0, ghB1;

        #define LOADROW(sfx, T)                                                     \
            {                                                                       \
                const int yin = y0 - 5 + (T);                                       \
                const bool rok = ((unsigned)yin < IMG);                             \
                const bool ok  = rok && cm_in;                                      \
                const int off = yin * IMG + cmain;                                  \
                pm##sfx##0 = ok ? p0[off] : 0.f;  pm##sfx##1 = ok ? p1[off] : 0.f;  \
                gm##sfx##0 = ok ? g0[off] : 0.f;  gm##sfx##1 = ok ? g1[off] : 0.f;  \
                const bool ok2 = rok && ch_in;                                      \
                const int off2 = yin * IMG + chalo;                                 \
                ph##sfx##0 = ok2 ? p0[off2] : 0.f; ph##sfx##1 = ok2 ? p1[off2] : 0.f;\
                gh##sfx##0 = ok2 ? g0[off2] : 0.f; gh##sfx##1 = ok2 ? g1[off2] : 0.f;\
            }

        LOADROW(A, 0)
        LOADROW(B, 1)
        __syncthreads();   // previous segment's readers of sv are done

        for (int op = 0; op * 11 < NP; ++op) {
            #pragma unroll
            for (int jj = 0; jj < 11; ++jj) {
                const int pair = op * 11 + jj;
                if (pair < NP) {
                    const int buf = pair & 1;
                    const int t0  = 2 * pair;
                    // ---- store raw rows (row B guarded for odd NIT) ----
                    sv[buf][0][tid] = make_float4(pmA0, pmA1, gmA0, gmA1);
                    if (t0 + 1 < NIT)
                        sv[buf][1][tid] = make_float4(pmB0, pmB1, gmB0, gmB1);
                    if (tid < 10) {
                        sv[buf][0][TX + tid] = make_float4(phA0, phA1, ghA0, ghA1);
                        if (t0 + 1 < NIT)
                            sv[buf][1][TX + tid] = make_float4(phB0, phB1, ghB0, ghB1);
                    }
                    // ---- prefetch next pair before the barrier ----
                    if (t0 + 2 < NIT) LOADROW(A, t0 + 2)
                    if (t0 + 3 < NIT) LOADROW(B, t0 + 3)
                    __syncthreads();

                    const int k0 = (2 * jj) % 11;
                    const int k1 = (2 * jj + 1) % 11;
                    #define HBLUR(ROW, KD)                                                      \
                        {                                                                       \
                            const float4* V = &sv[buf][ROW][tid];                               \
                            float4 cv = V[5];                                                   \
                            u64 pc = pk2(cv.x, cv.y), gc = pk2(cv.z, cv.w);                     \
                            u64 hP = f2mul(pc, w2[0]);                                          \
                            u64 hG = f2mul(gc, w2[0]);                                          \
                            u64 hS = f2mul(f2fma(gc, gc, f2mul(pc, pc)), w2[0]);                \
                            u64 hX = f2mul(f2mul(pc, gc), w2[0]);                               \
                            _Pragma("unroll")                                                   \
                            for (int d = 1; d <= 5; ++d) {                                      \
                                float4 Lv = V[5 - d], Rv = V[5 + d];                            \
                                u64 pl = pk2(Lv.x, Lv.y), gl = pk2(Lv.z, Lv.w);                 \
                                u64 pr = pk2(Rv.x, Rv.y), gr = pk2(Rv.z, Rv.w);                 \
                                hP = f2fma(f2add(pl, pr), w2[d], hP);                           \
                                hG = f2fma(f2add(gl, gr), w2[d], hG);                           \
                                u64 ss = f2fma(pr, pr, f2mul(pl, pl));                          \
                                ss = f2fma(gl, gl, ss);                                         \
                                ss = f2fma(gr, gr, ss);                                         \
                                hS = f2fma(ss, w2[d], hS);                                      \
                                hX = f2fma(f2fma(pr, gr, f2mul(pl, gl)), w2[d], hX);            \
                            }                                                                   \
                            rP[KD] = hP; rG[KD] = hG; rS[KD] = hS; rX[KD] = hX;                 \
                        }
                    HBLUR(0, k0)
                    if (t0 + 1 < NIT) HBLUR(1, k1)
                    #undef HBLUR

                    #define VS(K, JJ) (((K) + 6 + (JJ) + 11) % 11)
                    #define VBLUR(dst, r, K)                                           \
                        { u64 pa = f2fma(f2add(r[VS(K,-1)], r[VS(K,1)]), w2[1],        \
                                         f2mul(r[VS(K,0)], w2[0]));                    \
                          pa = f2fma(f2add(r[VS(K,-3)], r[VS(K,3)]), w2[3], pa);       \
                          u64 pb = f2mul(f2add(r[VS(K,-2)], r[VS(K,2)]), w2[2]);       \
                          pb = f2fma(f2add(r[VS(K,-4)], r[VS(K,4)]), w2[4], pb);       \
                          pb = f2fma(f2add(r[VS(K,-5)], r[VS(K,5)]), w2[5], pb);       \
                          dst = f2add(pa, pb); }
                    #define SSIMROW(K, ACC)                                            \
                        { u64 m1, m2, sS, s12;                                         \
                          VBLUR(m1,  rP, K); VBLUR(m2,  rG, K);                        \
                          VBLUR(sS,  rS, K); VBLUR(s12, rX, K);                        \
                          u64 m12 = f2mul(m1, m2);                                     \
                          u64 A  = f2fma(m12, two2, c1_2);                             \
                          u64 B  = f2fma(s12, two2, f2fma(m12, n2_2, c2_2));           \
                          u64 Cq = f2fma(m2, m2, f2fma(m1, m1, c1_2));                 \
                          u64 Dq = f2fma(Cq, n1_2, f2add(sS, c12_2));                  \
                          u64 num = f2mul(A, B);                                       \
                          u64 den = f2mul(Cq, Dq);                                     \
                          float na, nb, da, db;                                        \
                          unpk2(num, na, nb); unpk2(den, da, db);                      \
                          ACC = f2add(ACC, pk2(__fdividef(na, da),                     \
                                               __fdividef(nb, db))); }
                    if (t0 >= 10)                       SSIMROW(k0, acc0)
                    if (t0 + 1 >= 10 && t0 + 1 < NIT)   SSIMROW(k1, acc1)
                    #undef SSIMROW
                    #undef VBLUR
                    #undef VS
                }
            }
        }
        #undef LOADROW
        j += segout;
    }

    // ---- block reduction (deterministic partials, no float atomics) ----
    u64 accT = f2add(acc0, acc1);
    float a0, a1; unpk2(accT, a0, a1);
    float s = a0 + a1;
    #pragma unroll
    for (int o = 16; o > 0; o >>= 1) s += __shfl_xor_sync(0xffffffffu, s, o);
    if ((tid & 31) == 0) wred[tid >> 5] = s;
    __syncthreads();
    if (tid == 0) {
        double bs = 0.0;
        #pragma unroll
        for (int i = 0; i < TX / 32; ++i) bs += (double)wred[i];
        g_part[b] = bs;
        __threadfence();
        int old = atomicAdd(&g_cnt, 1);
        slast = (old == NBLK - 1) ? 1 : 0;
    }
    __syncthreads();

    // ---- last block finalizes (deterministic fixed-order double sum) ----
    if (slast) {
        __threadfence();
        double v = 0.0;
        #pragma unroll
        for (int i = 0; i < 4; ++i) {
            const int idx = tid + i * TX;
            if (idx < NBLK) v += g_part[idx];
        }
        #pragma unroll
        for (int o = 16; o > 0; o >>= 1) v += __shfl_xor_sync(0xffffffffu, v, o);
        __shared__ double sh[TX / 32];
        if ((tid & 31) == 0) sh[tid >> 5] = v;
        __syncthreads();
        if (tid == 0) {
            double tot = 0.0;
            #pragma unroll
            for (int i = 0; i < TX / 32; ++i) tot += sh[i];
            out[0] = (float)(1.0 - tot / ((double)NIMG * (double)PIX));
            g_cnt = 0;   // self-reset for graph replay
        }
    }
}

extern "C" void kernel_launch(void* const* d_in, const int* in_sizes, int n_in,
                              void* d_out, int out_size)
{
    const float* pred = (const float*)d_in[0];
    const float* gt   = (const float*)d_in[1];
    float* out = (float*)d_out;

    ssim_main<<<NBLK, TX>>>(pred, gt, out);
}

// round 9
// speedup vs baseline: 1.1945x; 1.1945x over previous
#include <cuda_runtime.h>
#include <math.h>

#define IMG   512
#define PIX   (IMG * IMG)
#define NIMG  64
#define TX    128
#define RPB   64
#define NITER (RPB + 10)            // 74 streamed rows per block
#define NPAIR (NITER / 2)           // 37 row pairs
#define WCOLS 44                    // 42 used + pad
#define GX    (IMG / TX)            // 4
#define GY    (IMG / RPB)           // 8
#define GZ    (NIMG / 2)            // 32 image pairs (f32x2 packing)
#define NBLK  (GX * GY * GZ)        // 1024

typedef unsigned long long u64;

__device__ double g_part[NBLK];
__device__ int    g_cnt;            // zero-initialized; self-resets each launch

static __device__ __forceinline__ u64 pk2(float a, float b) {
    u64 r; asm("mov.b64 %0, {%1, %2};" : "=l"(r) : "f"(a), "f"(b)); return r;
}
static __device__ __forceinline__ void unpk2(u64 v, float& a, float& b) {
    asm("mov.b64 {%0, %1}, %2;" : "=f"(a), "=f"(b) : "l"(v));
}
static __device__ __forceinline__ u64 f2add(u64 a, u64 b) {
    u64 d; asm("add.rn.f32x2 %0, %1, %2;" : "=l"(d) : "l"(a), "l"(b)); return d;
}
static __device__ __forceinline__ u64 f2mul(u64 a, u64 b) {
    u64 d; asm("mul.rn.f32x2 %0, %1, %2;" : "=l"(d) : "l"(a), "l"(b)); return d;
}
static __device__ __forceinline__ u64 f2fma(u64 a, u64 b, u64 c) {
    u64 d; asm("fma.rn.f32x2 %0, %1, %2, %3;" : "=l"(d) : "l"(a), "l"(b), "l"(c)); return d;
}

__global__ void __launch_bounds__(TX, 3) ssim_main(
    const float* __restrict__ pred, const float* __restrict__ gt,
    float* __restrict__ out)
{
    // Warp-private tiles: each warp owns a 32-column strip + 10-col halo in
    // its own double-buffered shared window. NO __syncthreads in the main
    // loop (only __syncwarp) — warps drift out of phase, so LDS-heavy hblur
    // of one warp overlaps fma-heavy vblur/ssim of another. Targets the
    // measured barrier phase-lock (issue 48%, both pipes ~50%).
    __shared__ float4 sw[TX / 32][2][2][WCOLS];   // [warp][buf][row][col]
    __shared__ float wred[TX / 32];
    __shared__ int   slast;

    const int tid  = threadIdx.x;
    const int wpid = tid >> 5;
    const int lane = tid & 31;
    const int cx   = blockIdx.x * TX + wpid * 32;   // warp's first output col
    const int ry0  = blockIdx.y * RPB;
    const int im0  = blockIdx.z;

    const float* p0 = pred + (size_t)im0 * PIX;
    const float* p1 = pred + (size_t)(im0 + NIMG / 2) * PIX;
    const float* g0 = gt   + (size_t)im0 * PIX;
    const float* g1 = gt   + (size_t)(im0 + NIMG / 2) * PIX;

    // Gaussian 1D weights (sigma = 11/6, normalized) — same math as reference
    float w[6];
    {
        const float sig = 11.0f / 6.0f;
        const float inv = 1.0f / (2.0f * sig * sig);
        float e[6];
        #pragma unroll
        for (int d = 0; d < 6; ++d) e[d] = expf(-(float)(d * d) * inv);
        float s = e[0] + 2.f * (e[1] + e[2] + e[3] + e[4] + e[5]);
        #pragma unroll
        for (int d = 0; d < 6; ++d) w[d] = e[d] / s;
    }
    u64 w2[6];
    #pragma unroll
    for (int d = 0; d < 6; ++d) w2[d] = pk2(w[d], w[d]);

    const float C1 = 0.01f * 0.01f;
    const float C2 = 0.03f * 0.03f;
    const u64 c1_2  = pk2(C1, C1);
    const u64 c2_2  = pk2(C2, C2);
    const u64 c12_2 = pk2(C1 + C2, C1 + C2);
    const u64 two2  = pk2(2.f, 2.f);
    const u64 n2_2  = pk2(-2.f, -2.f);
    const u64 n1_2  = pk2(-1.f, -1.f);

    // 11-row ring buffers of horizontally-blurred channels (registers)
    u64 rP[11], rG[11], rS[11], rX[11];
    u64 acc0 = 0ull, acc1 = 0ull;

    const int cmain = cx + lane - 5;         // cols cx-5 .. cx+26
    const int chalo = cx + 27 + lane;        // cols cx+27 .. cx+36 (lane<10)
    const bool cm_in = ((unsigned)cmain < IMG);
    const bool ch_in = ((unsigned)chalo < IMG) && (lane < 10);

    float pmA0, pmA1, gmA0, gmA1, phA0, phA1, ghA0, ghA1;
    float pmB0, pmB1, gmB0, gmB1, phB0, phB1, ghB0, ghB1;

    #define LOADROW(sfx, T)                                                     \
        {                                                                       \
            const int yin = ry0 - 5 + (T);                                      \
            const bool rok = ((unsigned)yin < IMG);                             \
            const bool ok  = rok && cm_in;                                      \
            const int off = yin * IMG + cmain;                                  \
            pm##sfx##0 = ok ? p0[off] : 0.f;  pm##sfx##1 = ok ? p1[off] : 0.f;  \
            gm##sfx##0 = ok ? g0[off] : 0.f;  gm##sfx##1 = ok ? g1[off] : 0.f;  \
            const bool ok2 = rok && ch_in;                                      \
            const int off2 = yin * IMG + chalo;                                 \
            ph##sfx##0 = ok2 ? p0[off2] : 0.f; ph##sfx##1 = ok2 ? p1[off2] : 0.f;\
            gh##sfx##0 = ok2 ? g0[off2] : 0.f; gh##sfx##1 = ok2 ? g1[off2] : 0.f;\
        }

    LOADROW(A, 0)
    LOADROW(B, 1)

    for (int outer = 0; outer < 4; ++outer) {
        #pragma unroll
        for (int j = 0; j < 11; ++j) {
            const int pair = outer * 11 + j;
            if (pair < NPAIR) {
                const int buf = pair & 1;
                // ---- store both raw rows into the warp's private window ----
                sw[wpid][buf][0][lane] = make_float4(pmA0, pmA1, gmA0, gmA1);
                sw[wpid][buf][1][lane] = make_float4(pmB0, pmB1, gmB0, gmB1);
                if (lane < 10) {
                    sw[wpid][buf][0][32 + lane] = make_float4(phA0, phA1, ghA0, ghA1);
                    sw[wpid][buf][1][32 + lane] = make_float4(phB0, phB1, ghB0, ghB1);
                }
                // ---- prefetch next pair (warp-local; no block barrier) ----
                const int t0 = 2 * pair;
                if (t0 + 2 < NITER) LOADROW(A, t0 + 2)
                if (t0 + 3 < NITER) LOADROW(B, t0 + 3)
                __syncwarp();

                const int k0 = (2 * j) % 11;
                const int k1 = (2 * j + 1) % 11;
                #define HBLUR(ROW, KD)                                                      \
                    {                                                                       \
                        const float4* V = &sw[wpid][buf][ROW][lane];                        \
                        float4 cv = V[5];                                                   \
                        u64 pc = pk2(cv.x, cv.y), gc = pk2(cv.z, cv.w);                     \
                        u64 hP = f2mul(pc, w2[0]);                                          \
                        u64 hG = f2mul(gc, w2[0]);                                          \
                        u64 hS = f2mul(f2fma(gc, gc, f2mul(pc, pc)), w2[0]);                \
                        u64 hX = f2mul(f2mul(pc, gc), w2[0]);                               \
                        _Pragma("unroll")                                                   \
                        for (int d = 1; d <= 5; ++d) {                                      \
                            float4 Lv = V[5 - d], Rv = V[5 + d];                            \
                            u64 pl = pk2(Lv.x, Lv.y), gl = pk2(Lv.z, Lv.w);                 \
                            u64 pr = pk2(Rv.x, Rv.y), gr = pk2(Rv.z, Rv.w);                 \
                            hP = f2fma(f2add(pl, pr), w2[d], hP);                           \
                            hG = f2fma(f2add(gl, gr), w2[d], hG);                           \
                            u64 ss = f2fma(pr, pr, f2mul(pl, pl));                          \
                            ss = f2fma(gl, gl, ss);                                         \
                            ss = f2fma(gr, gr, ss);                                         \
                            hS = f2fma(ss, w2[d], hS);                                      \
                            hX = f2fma(f2fma(pr, gr, f2mul(pl, gl)), w2[d], hX);            \
                        }                                                                   \
                        rP[KD] = hP; rG[KD] = hG; rS[KD] = hS; rX[KD] = hX;                 \
                    }
                HBLUR(0, k0)
                HBLUR(1, k1)
                #undef HBLUR

                if (pair >= 5) {
                    #define VS(K, JJ) (((K) + 6 + (JJ) + 11) % 11)
                    #define VBLUR(dst, r, K)                                           \
                        { u64 pa = f2fma(f2add(r[VS(K,-1)], r[VS(K,1)]), w2[1],        \
                                         f2mul(r[VS(K,0)], w2[0]));                    \
                          pa = f2fma(f2add(r[VS(K,-3)], r[VS(K,3)]), w2[3], pa);       \
                          u64 pb = f2mul(f2add(r[VS(K,-2)], r[VS(K,2)]), w2[2]);       \
                          pb = f2fma(f2add(r[VS(K,-4)], r[VS(K,4)]), w2[4], pb);       \
                          pb = f2fma(f2add(r[VS(K,-5)], r[VS(K,5)]), w2[5], pb);       \
                          dst = f2add(pa, pb); }
                    #define SSIMROW(K, ACC)                                            \
                        { u64 m1, m2, sS, s12;                                         \
                          VBLUR(m1,  rP, K); VBLUR(m2,  rG, K);                        \
                          VBLUR(sS,  rS, K); VBLUR(s12, rX, K);                        \
                          u64 m12 = f2mul(m1, m2);                                     \
                          u64 A  = f2fma(m12, two2, c1_2);                             \
                          u64 B  = f2fma(s12, two2, f2fma(m12, n2_2, c2_2));           \
                          u64 Cq = f2fma(m2, m2, f2fma(m1, m1, c1_2));                 \
                          u64 Dq = f2fma(Cq, n1_2, f2add(sS, c12_2));                  \
                          u64 num = f2mul(A, B);                                       \
                          u64 den = f2mul(Cq, Dq);                                     \
                          float na, nb, da, db;                                        \
                          unpk2(num, na, nb); unpk2(den, da, db);                      \
                          ACC = f2add(ACC, pk2(__fdividef(na, da),                     \
                                               __fdividef(nb, db))); }
                    SSIMROW(k0, acc0)
                    SSIMROW(k1, acc1)
                    #undef SSIMROW
                    #undef VBLUR
                    #undef VS
                }
            }
        }
    }
    #undef LOADROW

    // ---- block reduction (deterministic partials, no float atomics) ----
    u64 accT = f2add(acc0, acc1);
    float a0, a1; unpk2(accT, a0, a1);
    float s = a0 + a1;
    #pragma unroll
    for (int o = 16; o > 0; o >>= 1) s += __shfl_xor_sync(0xffffffffu, s, o);
    if (lane == 0) wred[wpid] = s;
    __syncthreads();
    if (tid == 0) {
        double bs = 0.0;
        #pragma unroll
        for (int i = 0; i < TX / 32; ++i) bs += (double)wred[i];
        const int bid = blockIdx.x + GX * (blockIdx.y + GY * blockIdx.z);
        g_part[bid] = bs;
        __threadfence();
        int old = atomicAdd(&g_cnt, 1);
        slast = (old == NBLK - 1) ? 1 : 0;
    }
    __syncthreads();

    // ---- last block finalizes (deterministic fixed-order double sum) ----
    if (slast) {
        __threadfence();
        double v = 0.0;
        #pragma unroll
        for (int i = 0; i < NBLK / TX; ++i)
            v += g_part[tid + i * TX];
        #pragma unroll
        for (int o = 16; o > 0; o >>= 1) v += __shfl_xor_sync(0xffffffffu, v, o);
        __shared__ double sh[TX / 32];
        if ((tid & 31) == 0) sh[tid >> 5] = v;
        __syncthreads();
        if (tid == 0) {
            double tot = 0.0;
            #pragma unroll
            for (int i = 0; i < TX / 32; ++i) tot += sh[i];
            out[0] = (float)(1.0 - tot / ((double)NIMG * (double)PIX));
            g_cnt = 0;   // self-reset for graph replay
        }
    }
}

extern "C" void kernel_launch(void* const* d_in, const int* in_sizes, int n_in,
                              void* d_out, int out_size)
{
    const float* pred = (const float*)d_in[0];
    const float* gt   = (const float*)d_in[1];
    float* out = (float*)d_out;

    dim3 grid(GX, GY, GZ);
    ssim_main<<<grid, TX>>>(pred, gt, out);
}